// round 16
// baseline (speedup 1.0000x reference)
#include <cuda_runtime.h>
#include <cuda_fp16.h>
#include <math.h>
#include <stdint.h>

// Problem constants (fixed by setup_inputs)
#define NN      262144
#define HH      192
#define SS      16384
#define IND     16
#define MAXDEG  32
#define KA      208          // extended K: [feat 16 | u 192]
#define NCHUNK  4            // pipeline chunks (2 samples each)

// ---------------- device scratch (no allocation allowed) -------------------
__device__ uint16_t g_ah[(size_t)NN * KA];   // A operand hi (all nodes)
__device__ uint16_t g_sh[(size_t)SS * KA];   // supernode rows hi (dense)
__device__ uint16_t g_sl[(size_t)SS * KA];   // supernode rows lo (dense)
__device__ __half   g_yh[(size_t)NN * HH];   // y = x @ W1_top (fp16)
__device__ float    g_z[(size_t)SS * HH];    // x_sup @ W1_bot + b1
__device__ uint16_t g_ph[(size_t)SS * HH];   // pooled GELU, fp16 hi
__device__ uint16_t g_pl[(size_t)SS * HH];   // pooled GELU, fp16 lo
__device__ float    g_v[2 * IND * HH];       // V = W_in @ W1_{top,bot}
// weight operands [n][k] fp16: slot 0 = [V1a|W1a], slot 1 = [V1b|W1b]
__device__ uint16_t g_b1h[2][HH * KA], g_b1l[2][HH * KA];
__device__ uint16_t g_b2h[HH * HH],  g_b2l[HH * HH];

// ---------------- helpers ---------------------------------------------------
__device__ __forceinline__ void split_f16(float x, uint16_t& h, uint16_t& l) {
    __half hh = __float2half_rn(x);
    h = __half_as_ushort(hh);
    l = __half_as_ushort(__float2half_rn(x - __half2float(hh)));
}

__device__ __forceinline__ void cp16(uint32_t s, const void* g) {
    asm volatile("cp.async.cg.shared.global [%0], [%1], 16;"
                 :: "r"(s), "l"(g));
}
__device__ __forceinline__ void cp_commit() {
    asm volatile("cp.async.commit_group;" ::: "memory");
}
template<int N>
__device__ __forceinline__ void cp_wait() {
    asm volatile("cp.async.wait_group %0;" :: "n"(N) : "memory");
}

__device__ __forceinline__ void ldm_x4(uint32_t addr, uint32_t r[4]) {
    asm volatile("ldmatrix.sync.aligned.m8n8.x4.shared.b16 {%0,%1,%2,%3}, [%4];"
                 : "=r"(r[0]), "=r"(r[1]), "=r"(r[2]), "=r"(r[3]) : "r"(addr));
}

__device__ __forceinline__ void mma_f16(float c[4], const uint32_t a[4],
                                        uint32_t b0, uint32_t b1) {
    asm volatile(
        "mma.sync.aligned.m16n8k16.row.col.f32.f16.f16.f32 "
        "{%0,%1,%2,%3}, {%4,%5,%6,%7}, {%8,%9}, {%0,%1,%2,%3};"
        : "+f"(c[0]), "+f"(c[1]), "+f"(c[2]), "+f"(c[3])
        : "r"(a[0]), "r"(a[1]), "r"(a[2]), "r"(a[3]), "r"(b0), "r"(b1));
}

// fast GELU: erf via Abramowitz-Stegun 7.1.26 (max abs err 1.5e-7)
__device__ __forceinline__ float rcp_fast(float x) {
    float r;
    asm("rcp.approx.f32 %0, %1;" : "=f"(r) : "f"(x));
    return r;
}
__device__ __forceinline__ float gelu_fast(float v) {
    float u = fabsf(v) * 0.70710678118654752f;
    float t = rcp_fast(fmaf(0.3275911f, u, 1.0f));
    float poly = fmaf(1.061405429f, t, -1.453152027f);
    poly = fmaf(poly, t, 1.421413741f);
    poly = fmaf(poly, t, -0.284496736f);
    poly = fmaf(poly, t, 0.254829592f);
    poly *= t;
    float e = __expf(-u * u);
    float erfv = fmaf(-poly, e, 1.0f);
    erfv = copysignf(erfv, v);
    return 0.5f * v * (1.0f + erfv);
}

// ---------------- GEMM shared-memory layouts --------------------------------
#define BUF_AH  0
#define BUF_AL  10240
#define BUF_BH  20480
#define BUF_BL  28160
#define BUF_SZ  35840
#define NBUF    3
#define SMEM_SZ (NBUF * BUF_SZ)      // 107520 -> 2 CTAs/SM

#define YBUF_B  10240
#define YBUF_SZ 25600
#define YSMEM_SZ (NBUF * YBUF_SZ)    // 76800 -> 2 CTAs/SM

// ---------------------------------------------------------------------------
// 3-term GEMM (z / out): C[M,192] = A @ B (+bias). CTA 128(M) x 96(N).
// m0base: row offset for chunked output GEMM.
// ---------------------------------------------------------------------------
template<int KCH, bool LASTHALF>
__global__ void __launch_bounds__(256, 2) gemm3_kernel(
    const uint16_t* __restrict__ Ah, const uint16_t* __restrict__ Al,
    const uint16_t* __restrict__ Bh, const uint16_t* __restrict__ Bl,
    const float* __restrict__ bias, float* __restrict__ C, int m0base)
{
    constexpr int AS = KCH * 32 - (LASTHALF ? 16 : 0);
    extern __shared__ char sm[];
    uint32_t sbase = (uint32_t)__cvta_generic_to_shared(sm);
    int tid = threadIdx.x;
    int lane = tid & 31;
    int wid = tid >> 5;
    int n0 = (blockIdx.x & 1) * 96;
    int m0 = m0base + (blockIdx.x >> 1) * 128;

    auto stage = [&](int kc, int buf) {
        int k0 = kc * 32;
        bool last = LASTHALF && (kc == KCH - 1);
        uint32_t sb = sbase + buf * BUF_SZ;
#pragma unroll
        for (int i = 0; i < 2; i++) {
            int id = tid + 256 * i;
            int row = id >> 2, j = id & 3;
            if (!last || j < 2) {
                size_t go = (size_t)(m0 + row) * AS + k0 + j * 8;
                uint32_t sa = sb + row * 80 + j * 16;
                cp16(sa, Ah + go);
                cp16(sa + BUF_AL, Al + go);
            }
        }
#pragma unroll
        for (int i = 0; i < 2; i++) {
            int id = tid + 256 * i;
            if (id < 384) {
                int row = id >> 2, j = id & 3;
                if (!last || j < 2) {
                    size_t go = (size_t)(n0 + row) * AS + k0 + j * 8;
                    uint32_t sa = sb + BUF_BH + row * 80 + j * 16;
                    cp16(sa, Bh + go);
                    cp16(sa + (BUF_BL - BUF_BH), Bl + go);
                }
            }
        }
    };

    float c[2][6][4];
#pragma unroll
    for (int mt = 0; mt < 2; mt++)
#pragma unroll
        for (int nt = 0; nt < 6; nt++)
#pragma unroll
            for (int k = 0; k < 4; k++) c[mt][nt][k] = 0.0f;

    int wm = wid >> 1;
    int wn = (wid & 1) * 48;
    uint32_t a_lrow = (lane & 7) + ((lane >> 3) & 1) * 8;
    uint32_t a_lcol = (lane >> 4) * 16;
    uint32_t b_lrow = (lane & 7) + (lane >> 4) * 8;
    uint32_t b_lcol = ((lane >> 3) & 1) * 16;

    stage(0, 0); cp_commit();
    stage(1, 1); cp_commit();

    for (int kc = 0; kc < KCH; kc++) {
        if (kc < KCH - 1) cp_wait<1>(); else cp_wait<0>();
        __syncthreads();
        if (kc < KCH - 2) { stage(kc + 2, (kc + 2) % NBUF); cp_commit(); }

        uint32_t sb = sbase + (kc % NBUF) * BUF_SZ;
        int ksmax = (LASTHALF && kc == KCH - 1) ? 1 : 2;
#pragma unroll
        for (int ks = 0; ks < 2; ks++) {
            if (ks >= ksmax) break;
            uint32_t ah[2][4], al[2][4];
#pragma unroll
            for (int mt = 0; mt < 2; mt++) {
                uint32_t ro = (wm * 32 + mt * 16 + a_lrow) * 80 + ks * 32 + a_lcol;
                ldm_x4(sb + ro, ah[mt]);
                ldm_x4(sb + BUF_AL + ro, al[mt]);
            }
#pragma unroll
            for (int np = 0; np < 3; np++) {
                uint32_t bo = (wn + np * 16 + b_lrow) * 80 + ks * 32 + b_lcol;
                uint32_t bh[4], bl[4];
                ldm_x4(sb + BUF_BH + bo, bh);
                ldm_x4(sb + BUF_BL + bo, bl);
#pragma unroll
                for (int mt = 0; mt < 2; mt++) {
                    mma_f16(c[mt][2 * np],     ah[mt], bh[0], bh[1]);
                    mma_f16(c[mt][2 * np],     al[mt], bh[0], bh[1]);
                    mma_f16(c[mt][2 * np],     ah[mt], bl[0], bl[1]);
                    mma_f16(c[mt][2 * np + 1], ah[mt], bh[2], bh[3]);
                    mma_f16(c[mt][2 * np + 1], al[mt], bh[2], bh[3]);
                    mma_f16(c[mt][2 * np + 1], ah[mt], bl[2], bl[3]);
                }
            }
        }
    }

    int r = lane >> 2, q = lane & 3;
#pragma unroll
    for (int mt = 0; mt < 2; mt++) {
        int row = m0 + wm * 32 + mt * 16 + r;
#pragma unroll
        for (int nt = 0; nt < 6; nt++) {
            int col = n0 + wn + nt * 8 + 2 * q;
            float b0 = bias ? bias[col] : 0.0f;
            float b1 = bias ? bias[col + 1] : 0.0f;
            *(float2*)(C + (size_t)row * HH + col) =
                make_float2(c[mt][nt][0] + b0, c[mt][nt][1] + b1);
            *(float2*)(C + (size_t)(row + 8) * HH + col) =
                make_float2(c[mt][nt][2] + b0, c[mt][nt][3] + b1);
        }
    }
}

// ---------------------------------------------------------------------------
// Single-term y-GEMM: y[M,192] = A_hi @ B_hi, fp16 out. CTA 128(M) x 192(N).
// ---------------------------------------------------------------------------
__global__ void __launch_bounds__(256, 2) gemm1_kernel(
    const uint16_t* __restrict__ Ah, const uint16_t* __restrict__ Bh,
    __half* __restrict__ C, int m0base)
{
    constexpr int KCH = 7;
    constexpr int AS = KA;
    extern __shared__ char sm[];
    uint32_t sbase = (uint32_t)__cvta_generic_to_shared(sm);
    int tid = threadIdx.x;
    int lane = tid & 31;
    int wid = tid >> 5;
    int m0 = m0base + blockIdx.x * 128;

    auto stage = [&](int kc, int buf) {
        int k0 = kc * 32;
        bool last = (kc == KCH - 1);
        uint32_t sb = sbase + buf * YBUF_SZ;
#pragma unroll
        for (int i = 0; i < 2; i++) {
            int id = tid + 256 * i;
            int row = id >> 2, j = id & 3;
            if (!last || j < 2) {
                size_t go = (size_t)(m0 + row) * AS + k0 + j * 8;
                cp16(sb + row * 80 + j * 16, Ah + go);
            }
        }
#pragma unroll
        for (int i = 0; i < 3; i++) {
            int id = tid + 256 * i;
            int row = id >> 2, j = id & 3;
            if (!last || j < 2) {
                size_t go = (size_t)row * AS + k0 + j * 8;
                cp16(sb + YBUF_B + row * 80 + j * 16, Bh + go);
            }
        }
    };

    float c[2][12][4];
#pragma unroll
    for (int mt = 0; mt < 2; mt++)
#pragma unroll
        for (int nt = 0; nt < 12; nt++)
#pragma unroll
            for (int k = 0; k < 4; k++) c[mt][nt][k] = 0.0f;

    int wm = wid >> 1;
    int wn = (wid & 1) * 96;
    uint32_t a_lrow = (lane & 7) + ((lane >> 3) & 1) * 8;
    uint32_t a_lcol = (lane >> 4) * 16;
    uint32_t b_lrow = (lane & 7) + (lane >> 4) * 8;
    uint32_t b_lcol = ((lane >> 3) & 1) * 16;

    stage(0, 0); cp_commit();
    stage(1, 1); cp_commit();

    for (int kc = 0; kc < KCH; kc++) {
        if (kc < KCH - 1) cp_wait<1>(); else cp_wait<0>();
        __syncthreads();
        if (kc < KCH - 2) { stage(kc + 2, (kc + 2) % NBUF); cp_commit(); }

        uint32_t sb = sbase + (kc % NBUF) * YBUF_SZ;
        int ksmax = (kc == KCH - 1) ? 1 : 2;
#pragma unroll
        for (int ks = 0; ks < 2; ks++) {
            if (ks >= ksmax) break;
            uint32_t ah[2][4];
#pragma unroll
            for (int mt = 0; mt < 2; mt++) {
                uint32_t ro = (wm * 32 + mt * 16 + a_lrow) * 80 + ks * 32 + a_lcol;
                ldm_x4(sb + ro, ah[mt]);
            }
#pragma unroll
            for (int np = 0; np < 6; np++) {
                uint32_t bo = (wn + np * 16 + b_lrow) * 80 + ks * 32 + b_lcol;
                uint32_t bh[4];
                ldm_x4(sb + YBUF_B + bo, bh);
#pragma unroll
                for (int mt = 0; mt < 2; mt++) {
                    mma_f16(c[mt][2 * np],     ah[mt], bh[0], bh[1]);
                    mma_f16(c[mt][2 * np + 1], ah[mt], bh[2], bh[3]);
                }
            }
        }
    }

    int r = lane >> 2, q = lane & 3;
#pragma unroll
    for (int mt = 0; mt < 2; mt++) {
        int row = m0 + wm * 32 + mt * 16 + r;
#pragma unroll
        for (int nt = 0; nt < 12; nt++) {
            int col = wn + nt * 8 + 2 * q;
            *(__half2*)(C + (size_t)row * HH + col) =
                __floats2half2_rn(c[mt][nt][0], c[mt][nt][1]);
            *(__half2*)(C + (size_t)(row + 8) * HH + col) =
                __floats2half2_rn(c[mt][nt][2], c[mt][nt][3]);
        }
    }
}

// ---------------------------------------------------------------------------
// Embed (all nodes): A row = [feat | b_in + sincos(pos)], HI ONLY.
// ---------------------------------------------------------------------------
__global__ void embed_kernel(const float* __restrict__ feat,
                             const float* __restrict__ pos,
                             const float* __restrict__ b_in, int nbase) {
    int n0 = nbase + blockIdx.x * 16;
    int tid = threadIdx.x;
    __shared__ float f[16][IND];
    __shared__ float p[16][3];
    for (int id = tid; id < 16 * IND; id += 208)
        f[id >> 4][id & 15] = feat[(n0 + (id >> 4)) * IND + (id & 15)];
    if (tid < 48) p[tid / 3][tid % 3] = pos[(n0 + tid / 3) * 3 + tid % 3];

    int sub = tid / 104;
    int cp = tid % 104;
    int c = 2 * cp;
    bool isfeat = (c < 16);
    int d = 0;
    float om0 = 0.f, om1 = 0.f, b0 = 0.f, b1 = 0.f;
    bool issin = true;
    if (!isfeat) {
        int cu = c - 16;
        d = cu >> 6;
        int t = cu & 63;
        int j = t & 31;
        om0 = exp2f(-(float)j * (13.2877123795494f / 32.0f));
        om1 = exp2f(-(float)(j + 1) * (13.2877123795494f / 32.0f));
        issin = (t < 32);
        b0 = b_in[cu];
        b1 = b_in[cu + 1];
    }
    __syncthreads();

    for (int nn = sub; nn < 16; nn += 2) {
        float v0, v1;
        if (isfeat) {
            v0 = f[nn][c]; v1 = f[nn][c + 1];
        } else {
            float pd = p[nn][d];
            float a0 = pd * om0, a1 = pd * om1;
            v0 = b0 + (issin ? __sinf(a0) : __cosf(a0));
            v1 = b1 + (issin ? __sinf(a1) : __cosf(a1));
        }
        *(__half2*)(g_ah + (size_t)(n0 + nn) * KA + c) =
            __floats2half2_rn(v0, v1);
    }
}

// ---------------------------------------------------------------------------
// Sup-embed: supernode rows only, hi+lo split, dense [SS,KA].
// ---------------------------------------------------------------------------
__global__ void sup_embed_kernel(const float* __restrict__ feat,
                                 const float* __restrict__ pos,
                                 const float* __restrict__ b_in,
                                 const int* __restrict__ sup) {
    int s0 = blockIdx.x * 16;
    int tid = threadIdx.x;
    __shared__ int nid[16];
    __shared__ float f[16][IND];
    __shared__ float p[16][3];
    if (tid < 16) nid[tid] = sup[s0 + tid];
    __syncthreads();
    for (int id = tid; id < 16 * IND; id += 208)
        f[id >> 4][id & 15] = feat[nid[id >> 4] * IND + (id & 15)];
    if (tid < 48) p[tid / 3][tid % 3] = pos[nid[tid / 3] * 3 + tid % 3];

    int sub = tid / 104;
    int cp = tid % 104;
    int c = 2 * cp;
    bool isfeat = (c < 16);
    int d = 0;
    float om0 = 0.f, om1 = 0.f, b0 = 0.f, b1 = 0.f;
    bool issin = true;
    if (!isfeat) {
        int cu = c - 16;
        d = cu >> 6;
        int t = cu & 63;
        int j = t & 31;
        om0 = exp2f(-(float)j * (13.2877123795494f / 32.0f));
        om1 = exp2f(-(float)(j + 1) * (13.2877123795494f / 32.0f));
        issin = (t < 32);
        b0 = b_in[cu];
        b1 = b_in[cu + 1];
    }
    __syncthreads();

    for (int nn = sub; nn < 16; nn += 2) {
        float v0, v1;
        if (isfeat) {
            v0 = f[nn][c]; v1 = f[nn][c + 1];
        } else {
            float pd = p[nn][d];
            float a0 = pd * om0, a1 = pd * om1;
            v0 = b0 + (issin ? __sinf(a0) : __cosf(a0));
            v1 = b1 + (issin ? __sinf(a1) : __cosf(a1));
        }
        uint16_t h0, l0, h1, l1;
        split_f16(v0, h0, l0);
        split_f16(v1, h1, l1);
        size_t o = (size_t)(s0 + nn) * KA + c;
        *(uint32_t*)(g_sh + o) = (uint32_t)h0 | ((uint32_t)h1 << 16);
        *(uint32_t*)(g_sl + o) = (uint32_t)l0 | ((uint32_t)l1 << 16);
    }
}

// ---------------------------------------------------------------------------
// V = W_in @ W1_{top,bot}: grid 32 (s*16+i), block 192 (n)
// ---------------------------------------------------------------------------
__global__ void vprep_kernel(const float* __restrict__ W_in,
                             const float* __restrict__ W1) {
    int s = blockIdx.x >> 4, i = blockIdx.x & 15, n = threadIdx.x;
    float acc = 0.0f;
    for (int cc = 0; cc < HH; cc++)
        acc = fmaf(W_in[i * HH + cc], W1[(size_t)(cc + s * HH) * HH + n], acc);
    g_v[(s * IND + i) * HH + n] = acc;
}

// ---------------------------------------------------------------------------
// B operands: s<2 -> [V|W1] (KA cols), s==2 -> W2 (HH cols). grid (192,3).
// ---------------------------------------------------------------------------
__global__ void bprep_kernel(const float* __restrict__ W1,
                             const float* __restrict__ W2) {
    int n = blockIdx.x, s = blockIdx.y, k = threadIdx.x;
    if (s < 2) {
        float v = (k < IND) ? g_v[(s * IND + k) * HH + n]
                            : W1[(size_t)(k - IND + s * HH) * HH + n];
        uint16_t h, l;
        split_f16(v, h, l);
        g_b1h[s][n * KA + k] = h;
        g_b1l[s][n * KA + k] = l;
    } else if (k < HH) {
        uint16_t h, l;
        split_f16(W2[(size_t)k * HH + n], h, l);
        g_b2h[n * HH + k] = h;
        g_b2l[n * HH + k] = l;
    }
}

// ---------------------------------------------------------------------------
// Pool: pool[s,c] = mean_e GELU(y[src_e,c] + z[s,c]); split fp16 output.
// ---------------------------------------------------------------------------
__global__ void pool_kernel(const int* __restrict__ src_idx, int sbase) {
    int tid = threadIdx.x;
    int sgrp = tid / 48;
    int t = tid % 48;
    int sblk = sbase + blockIdx.x * 4;
    int s = sblk + sgrp;
    int c = t * 4;

    __shared__ int srcs[4][MAXDEG];
    if (tid < 128) srcs[tid >> 5][tid & 31] = src_idx[sblk * MAXDEG + tid];
    __syncthreads();

    float4 z = *(const float4*)(g_z + (size_t)s * HH + c);
    float4 acc = make_float4(0.f, 0.f, 0.f, 0.f);
#pragma unroll 4
    for (int e = 0; e < MAXDEG; e++) {
        const __half2* yr = (const __half2*)(g_yh + (size_t)srcs[sgrp][e] * HH + c);
        float2 v01 = __half22float2(yr[0]);
        float2 v23 = __half22float2(yr[1]);
        acc.x += gelu_fast(v01.x + z.x);
        acc.y += gelu_fast(v01.y + z.y);
        acc.z += gelu_fast(v23.x + z.z);
        acc.w += gelu_fast(v23.y + z.w);
    }
    const float inv = 1.0f / 32.0f;
    uint16_t h[4], l[4];
    split_f16(acc.x * inv, h[0], l[0]);
    split_f16(acc.y * inv, h[1], l[1]);
    split_f16(acc.z * inv, h[2], l[2]);
    split_f16(acc.w * inv, h[3], l[3]);
    size_t o = (size_t)s * HH + c;
    *(uint2*)(g_ph + o) = make_uint2((uint32_t)h[0] | ((uint32_t)h[1] << 16),
                                     (uint32_t)h[2] | ((uint32_t)h[3] << 16));
    *(uint2*)(g_pl + o) = make_uint2((uint32_t)l[0] | ((uint32_t)l[1] << 16),
                                     (uint32_t)l[2] | ((uint32_t)l[3] << 16));
}

// ---------------------------------------------------------------------------
// launch: chunked 3-stream pipeline.
//   s0: prep, embed chunks            (evE[c])
//   s1: y chunks (wait evE), out chunks (wait evP)
//   s2: sup_embed + z, pool chunks (wait evY)  (evP[c])
// ---------------------------------------------------------------------------
static cudaStream_t g_s1 = nullptr, g_s2 = nullptr;
static cudaEvent_t  g_evFork = nullptr, g_evEnd = nullptr;
static cudaEvent_t  g_evE[NCHUNK], g_evY[NCHUNK], g_evP[NCHUNK];

extern "C" void kernel_launch(void* const* d_in, const int* in_sizes, int n_in,
                              void* d_out, int out_size) {
    const float* feat  = (const float*)d_in[0];
    const float* pos   = (const float*)d_in[1];
    const int*   sup   = (const int*)  d_in[2];
    const int*   src   = (const int*)  d_in[4];
    const float* W_in  = (const float*)d_in[6];
    const float* b_in  = (const float*)d_in[7];
    const float* W1    = (const float*)d_in[8];
    const float* b1    = (const float*)d_in[9];
    const float* W2    = (const float*)d_in[10];
    const float* b2    = (const float*)d_in[11];
    float* out = (float*)d_out;

    if (g_s1 == nullptr) {
        cudaStreamCreateWithFlags(&g_s1, cudaStreamNonBlocking);
        cudaStreamCreateWithFlags(&g_s2, cudaStreamNonBlocking);
        cudaEventCreateWithFlags(&g_evFork, cudaEventDisableTiming);
        cudaEventCreateWithFlags(&g_evEnd,  cudaEventDisableTiming);
        for (int c = 0; c < NCHUNK; c++) {
            cudaEventCreateWithFlags(&g_evE[c], cudaEventDisableTiming);
            cudaEventCreateWithFlags(&g_evY[c], cudaEventDisableTiming);
            cudaEventCreateWithFlags(&g_evP[c], cudaEventDisableTiming);
        }
    }

    uint16_t *pah, *psh, *psl, *pph, *ppl, *pb1h, *pb1l, *pb2h, *pb2l;
    __half *pyh;
    float *pz;
    cudaGetSymbolAddress((void**)&pah,  g_ah);
    cudaGetSymbolAddress((void**)&psh,  g_sh);
    cudaGetSymbolAddress((void**)&psl,  g_sl);
    cudaGetSymbolAddress((void**)&pyh,  g_yh);
    cudaGetSymbolAddress((void**)&pz,   g_z);
    cudaGetSymbolAddress((void**)&pph,  g_ph);
    cudaGetSymbolAddress((void**)&ppl,  g_pl);
    cudaGetSymbolAddress((void**)&pb1h, g_b1h);
    cudaGetSymbolAddress((void**)&pb1l, g_b1l);
    cudaGetSymbolAddress((void**)&pb2h, g_b2h);
    cudaGetSymbolAddress((void**)&pb2l, g_b2l);

    cudaFuncSetAttribute((const void*)gemm3_kernel<7, true>,
                         cudaFuncAttributeMaxDynamicSharedMemorySize, SMEM_SZ);
    cudaFuncSetAttribute((const void*)gemm3_kernel<6, false>,
                         cudaFuncAttributeMaxDynamicSharedMemorySize, SMEM_SZ);
    cudaFuncSetAttribute((const void*)gemm1_kernel,
                         cudaFuncAttributeMaxDynamicSharedMemorySize, YSMEM_SZ);

    const int NPC = NN / NCHUNK;      // nodes per chunk   (65536)
    const int SPC = SS / NCHUNK;      // supernodes/chunk  (4096)

    // prep chain on s0
    vprep_kernel<<<32, HH>>>(W_in, W1);
    bprep_kernel<<<dim3(HH, 3), KA>>>(W1, W2);
    cudaEventRecord(g_evFork, 0);

    // s2: z path (needs bprep)
    cudaStreamWaitEvent(g_s2, g_evFork, 0);
    sup_embed_kernel<<<SS / 16, KA, 0, g_s2>>>(feat, pos, b_in, sup);
    gemm3_kernel<7, true><<<(SS / 128) * 2, 256, SMEM_SZ, g_s2>>>(
        psh, psl, pb1h + HH * KA, pb1l + HH * KA, b1, pz, 0);

    // s1 needs bprep for y-GEMM B operand
    cudaStreamWaitEvent(g_s1, g_evFork, 0);

    for (int c = 0; c < NCHUNK; c++) {
        // s0: embed chunk
        embed_kernel<<<NPC / 16, KA>>>(feat, pos, b_in, c * NPC);
        cudaEventRecord(g_evE[c], 0);
        // s1: y chunk
        cudaStreamWaitEvent(g_s1, g_evE[c], 0);
        gemm1_kernel<<<NPC / 128, 256, YSMEM_SZ, g_s1>>>(
            pah, pb1h, pyh, c * NPC);
        cudaEventRecord(g_evY[c], g_s1);
        // s2: pool chunk (z already ordered earlier on s2)
        cudaStreamWaitEvent(g_s2, g_evY[c], 0);
        pool_kernel<<<SPC / 4, HH, 0, g_s2>>>(src, c * SPC);
        cudaEventRecord(g_evP[c], g_s2);
    }

    // out chunks on s1 (after its y chunks; each waits its pool chunk)
    for (int c = 0; c < NCHUNK; c++) {
        cudaStreamWaitEvent(g_s1, g_evP[c], 0);
        gemm3_kernel<6, false><<<(SPC / 128) * 2, 256, SMEM_SZ, g_s1>>>(
            pph, ppl, pb2h, pb2l, b2, out, c * SPC);
    }
    cudaEventRecord(g_evEnd, g_s1);
    cudaStreamWaitEvent(0, g_evEnd, 0);
}

// round 17
// speedup vs baseline: 1.1777x; 1.1777x over previous
#include <cuda_runtime.h>
#include <cuda_fp16.h>
#include <math.h>
#include <stdint.h>

// Problem constants (fixed by setup_inputs)
#define NN      262144
#define HH      192
#define SS      16384
#define IND     16
#define MAXDEG  32
#define KA      208          // extended K: [feat 16 | u 192]

// ---------------- device scratch (no allocation allowed) -------------------
__device__ uint16_t g_sh[(size_t)SS * KA];   // supernode rows hi (dense)
__device__ uint16_t g_sl[(size_t)SS * KA];   // supernode rows lo (dense)
__device__ __half   g_yh[(size_t)NN * HH];   // y = x @ W1_top (fp16)
__device__ float    g_z[(size_t)SS * HH];    // x_sup @ W1_bot + b1
__device__ uint16_t g_ph[(size_t)SS * HH];   // pooled GELU, fp16 hi
__device__ uint16_t g_pl[(size_t)SS * HH];   // pooled GELU, fp16 lo
__device__ float    g_v[2 * IND * HH];       // V = W_in @ W1_{top,bot}
// weight operands [n][k] fp16: slot 0 = [V1a|W1a], slot 1 = [V1b|W1b]
__device__ uint16_t g_b1h[2][HH * KA], g_b1l[2][HH * KA];
__device__ uint16_t g_b2h[HH * HH],  g_b2l[HH * HH];

// ---------------- helpers ---------------------------------------------------
__device__ __forceinline__ void split_f16(float x, uint16_t& h, uint16_t& l) {
    __half hh = __float2half_rn(x);
    h = __half_as_ushort(hh);
    l = __half_as_ushort(__float2half_rn(x - __half2float(hh)));
}

__device__ __forceinline__ void cp16(uint32_t s, const void* g) {
    asm volatile("cp.async.cg.shared.global [%0], [%1], 16;"
                 :: "r"(s), "l"(g));
}
__device__ __forceinline__ void cp_commit() {
    asm volatile("cp.async.commit_group;" ::: "memory");
}
template<int N>
__device__ __forceinline__ void cp_wait() {
    asm volatile("cp.async.wait_group %0;" :: "n"(N) : "memory");
}

__device__ __forceinline__ void ldm_x4(uint32_t addr, uint32_t r[4]) {
    asm volatile("ldmatrix.sync.aligned.m8n8.x4.shared.b16 {%0,%1,%2,%3}, [%4];"
                 : "=r"(r[0]), "=r"(r[1]), "=r"(r[2]), "=r"(r[3]) : "r"(addr));
}

__device__ __forceinline__ void mma_f16(float c[4], const uint32_t a[4],
                                        uint32_t b0, uint32_t b1) {
    asm volatile(
        "mma.sync.aligned.m16n8k16.row.col.f32.f16.f16.f32 "
        "{%0,%1,%2,%3}, {%4,%5,%6,%7}, {%8,%9}, {%0,%1,%2,%3};"
        : "+f"(c[0]), "+f"(c[1]), "+f"(c[2]), "+f"(c[3])
        : "r"(a[0]), "r"(a[1]), "r"(a[2]), "r"(a[3]), "r"(b0), "r"(b1));
}

// fast GELU: erf via Abramowitz-Stegun 7.1.26 (max abs err 1.5e-7)
__device__ __forceinline__ float rcp_fast(float x) {
    float r;
    asm("rcp.approx.f32 %0, %1;" : "=f"(r) : "f"(x));
    return r;
}
__device__ __forceinline__ float gelu_fast(float v) {
    float u = fabsf(v) * 0.70710678118654752f;
    float t = rcp_fast(fmaf(0.3275911f, u, 1.0f));
    float poly = fmaf(1.061405429f, t, -1.453152027f);
    poly = fmaf(poly, t, 1.421413741f);
    poly = fmaf(poly, t, -0.284496736f);
    poly = fmaf(poly, t, 0.254829592f);
    poly *= t;
    float e = __expf(-u * u);
    float erfv = fmaf(-poly, e, 1.0f);
    erfv = copysignf(erfv, v);
    return 0.5f * v * (1.0f + erfv);
}

// ---------------- GEMM shared-memory layouts --------------------------------
#define BUF_AH  0
#define BUF_AL  10240
#define BUF_BH  20480
#define BUF_BL  28160
#define BUF_SZ  35840
#define NBUF    3
#define SMEM_SZ (NBUF * BUF_SZ)      // 107520 -> 2 CTAs/SM

#define YBUF_B  10240
#define YBUF_SZ 25600
// fused-y constants live after the 3 pipeline buffers
#define YOFF_OM  (NBUF * YBUF_SZ)          // 76800: omega[192] f32
#define YOFF_BB  (YOFF_OM + 768)           // 77568: b_in[192] f32
#define YOFF_POS (YOFF_BB + 768)           // 78336: pos[128*3] f32
#define YSMEM_SZ (YOFF_POS + 1536)         // 79872 -> 2 CTAs/SM

// ---------------------------------------------------------------------------
// 3-term GEMM (z / out): C[M,192] = A @ B (+bias). CTA 128(M) x 96(N).
// ---------------------------------------------------------------------------
template<int KCH, bool LASTHALF>
__global__ void __launch_bounds__(256, 2) gemm3_kernel(
    const uint16_t* __restrict__ Ah, const uint16_t* __restrict__ Al,
    const uint16_t* __restrict__ Bh, const uint16_t* __restrict__ Bl,
    const float* __restrict__ bias, float* __restrict__ C)
{
    constexpr int AS = KCH * 32 - (LASTHALF ? 16 : 0);
    extern __shared__ char sm[];
    uint32_t sbase = (uint32_t)__cvta_generic_to_shared(sm);
    int tid = threadIdx.x;
    int lane = tid & 31;
    int wid = tid >> 5;
    int n0 = (blockIdx.x & 1) * 96;
    int m0 = (blockIdx.x >> 1) * 128;

    auto stage = [&](int kc, int buf) {
        int k0 = kc * 32;
        bool last = LASTHALF && (kc == KCH - 1);
        uint32_t sb = sbase + buf * BUF_SZ;
#pragma unroll
        for (int i = 0; i < 2; i++) {
            int id = tid + 256 * i;
            int row = id >> 2, j = id & 3;
            if (!last || j < 2) {
                size_t go = (size_t)(m0 + row) * AS + k0 + j * 8;
                uint32_t sa = sb + row * 80 + j * 16;
                cp16(sa, Ah + go);
                cp16(sa + BUF_AL, Al + go);
            }
        }
#pragma unroll
        for (int i = 0; i < 2; i++) {
            int id = tid + 256 * i;
            if (id < 384) {
                int row = id >> 2, j = id & 3;
                if (!last || j < 2) {
                    size_t go = (size_t)(n0 + row) * AS + k0 + j * 8;
                    uint32_t sa = sb + BUF_BH + row * 80 + j * 16;
                    cp16(sa, Bh + go);
                    cp16(sa + (BUF_BL - BUF_BH), Bl + go);
                }
            }
        }
    };

    float c[2][6][4];
#pragma unroll
    for (int mt = 0; mt < 2; mt++)
#pragma unroll
        for (int nt = 0; nt < 6; nt++)
#pragma unroll
            for (int k = 0; k < 4; k++) c[mt][nt][k] = 0.0f;

    int wm = wid >> 1;
    int wn = (wid & 1) * 48;
    uint32_t a_lrow = (lane & 7) + ((lane >> 3) & 1) * 8;
    uint32_t a_lcol = (lane >> 4) * 16;
    uint32_t b_lrow = (lane & 7) + (lane >> 4) * 8;
    uint32_t b_lcol = ((lane >> 3) & 1) * 16;

    stage(0, 0); cp_commit();
    stage(1, 1); cp_commit();

    for (int kc = 0; kc < KCH; kc++) {
        if (kc < KCH - 1) cp_wait<1>(); else cp_wait<0>();
        __syncthreads();
        if (kc < KCH - 2) { stage(kc + 2, (kc + 2) % NBUF); cp_commit(); }

        uint32_t sb = sbase + (kc % NBUF) * BUF_SZ;
        int ksmax = (LASTHALF && kc == KCH - 1) ? 1 : 2;
#pragma unroll
        for (int ks = 0; ks < 2; ks++) {
            if (ks >= ksmax) break;
            uint32_t ah[2][4], al[2][4];
#pragma unroll
            for (int mt = 0; mt < 2; mt++) {
                uint32_t ro = (wm * 32 + mt * 16 + a_lrow) * 80 + ks * 32 + a_lcol;
                ldm_x4(sb + ro, ah[mt]);
                ldm_x4(sb + BUF_AL + ro, al[mt]);
            }
#pragma unroll
            for (int np = 0; np < 3; np++) {
                uint32_t bo = (wn + np * 16 + b_lrow) * 80 + ks * 32 + b_lcol;
                uint32_t bh[4], bl[4];
                ldm_x4(sb + BUF_BH + bo, bh);
                ldm_x4(sb + BUF_BL + bo, bl);
#pragma unroll
                for (int mt = 0; mt < 2; mt++) {
                    mma_f16(c[mt][2 * np],     ah[mt], bh[0], bh[1]);
                    mma_f16(c[mt][2 * np],     al[mt], bh[0], bh[1]);
                    mma_f16(c[mt][2 * np],     ah[mt], bl[0], bl[1]);
                    mma_f16(c[mt][2 * np + 1], ah[mt], bh[2], bh[3]);
                    mma_f16(c[mt][2 * np + 1], al[mt], bh[2], bh[3]);
                    mma_f16(c[mt][2 * np + 1], ah[mt], bl[2], bl[3]);
                }
            }
        }
    }

    int r = lane >> 2, q = lane & 3;
#pragma unroll
    for (int mt = 0; mt < 2; mt++) {
        int row = m0 + wm * 32 + mt * 16 + r;
#pragma unroll
        for (int nt = 0; nt < 6; nt++) {
            int col = n0 + wn + nt * 8 + 2 * q;
            float b0 = bias ? bias[col] : 0.0f;
            float b1 = bias ? bias[col + 1] : 0.0f;
            *(float2*)(C + (size_t)row * HH + col) =
                make_float2(c[mt][nt][0] + b0, c[mt][nt][1] + b1);
            *(float2*)(C + (size_t)(row + 8) * HH + col) =
                make_float2(c[mt][nt][2] + b0, c[mt][nt][3] + b1);
        }
    }
}

// ---------------------------------------------------------------------------
// Fused embed + single-term y-GEMM: y = [feat | b_in+sincos(pos)] @ B_hi.
// A tile computed on the fly into SMEM (each A row touched by exactly 1 CTA).
// CTA 128(M) x 192(N), 8 warps of 32x96. B staged via cp.async (unchanged).
// ---------------------------------------------------------------------------
__global__ void __launch_bounds__(256, 2) gemm1f_kernel(
    const float* __restrict__ feat, const float* __restrict__ pos,
    const float* __restrict__ b_in, const uint16_t* __restrict__ Bh,
    __half* __restrict__ C)
{
    constexpr int KCH = 7;            // 7 chunks, last has 16 valid k
    extern __shared__ char sm[];
    uint32_t sbase = (uint32_t)__cvta_generic_to_shared(sm);
    float* om_s  = (float*)(sm + YOFF_OM);
    float* bb_s  = (float*)(sm + YOFF_BB);
    float* pos_s = (float*)(sm + YOFF_POS);
    int tid = threadIdx.x;
    int lane = tid & 31;
    int wid = tid >> 5;
    int m0 = blockIdx.x * 128;

    // per-CTA constants: omega, b_in, pos rows
    if (tid < HH) {
        om_s[tid] = exp2f(-(float)(tid & 31) * (13.2877123795494f / 32.0f));
        bb_s[tid] = b_in[tid];
    }
    for (int id = tid; id < 128 * 3; id += 256)
        pos_s[id] = pos[(size_t)(m0 + id / 3) * 3 + id % 3];
    __syncthreads();

    // A staging: compute [feat | u] fp16 directly into smem buffer.
    // thread t -> row = t>>1, k-half = t&1 (16 cols).
    auto stageA = [&](int kc, int buf) {
        int row = tid >> 1, half = tid & 1;
        if (kc == KCH - 1 && half == 1) return;     // pad half of last chunk
        char* dst = sm + buf * YBUF_SZ + row * 80 + half * 32;
        if (kc == 0 && half == 0) {
            const float4* fr = (const float4*)(feat + (size_t)(m0 + row) * IND);
#pragma unroll
            for (int i = 0; i < 4; i++) {
                float4 v = fr[i];
                *(__half2*)(dst + i * 8 + 0) = __floats2half2_rn(v.x, v.y);
                *(__half2*)(dst + i * 8 + 4) = __floats2half2_rn(v.z, v.w);
            }
        } else {
            int cu0 = kc * 32 + half * 16 - 16;     // 16-aligned, d & phase const
            int d = cu0 >> 6;
            float ph = ((cu0 & 63) < 32) ? 0.0f : 1.5707963267948966f;
            float pd = pos_s[row * 3 + d];
#pragma unroll
            for (int i = 0; i < 16; i += 2) {
                float v0 = bb_s[cu0 + i]     + __sinf(fmaf(pd, om_s[cu0 + i],     ph));
                float v1 = bb_s[cu0 + i + 1] + __sinf(fmaf(pd, om_s[cu0 + i + 1], ph));
                *(__half2*)(dst + i * 2) = __floats2half2_rn(v0, v1);
            }
        }
    };
    auto stageB = [&](int kc, int buf) {
        int k0 = kc * 32;
        bool last = (kc == KCH - 1);
        uint32_t sb = sbase + buf * YBUF_SZ;
#pragma unroll
        for (int i = 0; i < 3; i++) {             // B: 768 ids
            int id = tid + 256 * i;
            int row = id >> 2, j = id & 3;
            if (!last || j < 2) {
                size_t go = (size_t)row * KA + k0 + j * 8;
                cp16(sb + YBUF_B + row * 80 + j * 16, Bh + go);
            }
        }
    };

    float c[2][12][4];
#pragma unroll
    for (int mt = 0; mt < 2; mt++)
#pragma unroll
        for (int nt = 0; nt < 12; nt++)
#pragma unroll
            for (int k = 0; k < 4; k++) c[mt][nt][k] = 0.0f;

    int wm = wid >> 1;
    int wn = (wid & 1) * 96;
    uint32_t a_lrow = (lane & 7) + ((lane >> 3) & 1) * 8;
    uint32_t a_lcol = (lane >> 4) * 16;
    uint32_t b_lrow = (lane & 7) + (lane >> 4) * 8;
    uint32_t b_lcol = ((lane >> 3) & 1) * 16;

    stageA(0, 0); stageB(0, 0); cp_commit();
    stageA(1, 1); stageB(1, 1); cp_commit();

    for (int kc = 0; kc < KCH; kc++) {
        if (kc < KCH - 1) cp_wait<1>(); else cp_wait<0>();
        __syncthreads();      // orders STS(A) of kc..kc+1 and prior reads
        if (kc < KCH - 2) {
            stageA(kc + 2, (kc + 2) % NBUF);
            stageB(kc + 2, (kc + 2) % NBUF);
            cp_commit();
        }

        uint32_t sb = sbase + (kc % NBUF) * YBUF_SZ;
        int ksmax = (kc == KCH - 1) ? 1 : 2;
#pragma unroll
        for (int ks = 0; ks < 2; ks++) {
            if (ks >= ksmax) break;
            uint32_t ah[2][4];
#pragma unroll
            for (int mt = 0; mt < 2; mt++) {
                uint32_t ro = (wm * 32 + mt * 16 + a_lrow) * 80 + ks * 32 + a_lcol;
                ldm_x4(sb + ro, ah[mt]);
            }
#pragma unroll
            for (int np = 0; np < 6; np++) {
                uint32_t bo = (wn + np * 16 + b_lrow) * 80 + ks * 32 + b_lcol;
                uint32_t bh[4];
                ldm_x4(sb + YBUF_B + bo, bh);
#pragma unroll
                for (int mt = 0; mt < 2; mt++) {
                    mma_f16(c[mt][2 * np],     ah[mt], bh[0], bh[1]);
                    mma_f16(c[mt][2 * np + 1], ah[mt], bh[2], bh[3]);
                }
            }
        }
    }

    int r = lane >> 2, q = lane & 3;
#pragma unroll
    for (int mt = 0; mt < 2; mt++) {
        int row = m0 + wm * 32 + mt * 16 + r;
#pragma unroll
        for (int nt = 0; nt < 12; nt++) {
            int col = wn + nt * 8 + 2 * q;
            *(__half2*)(C + (size_t)row * HH + col) =
                __floats2half2_rn(c[mt][nt][0], c[mt][nt][1]);
            *(__half2*)(C + (size_t)(row + 8) * HH + col) =
                __floats2half2_rn(c[mt][nt][2], c[mt][nt][3]);
        }
    }
}

// ---------------------------------------------------------------------------
// Sup-embed: supernode rows only, hi+lo split, dense [SS,KA].
// ---------------------------------------------------------------------------
__global__ void sup_embed_kernel(const float* __restrict__ feat,
                                 const float* __restrict__ pos,
                                 const float* __restrict__ b_in,
                                 const int* __restrict__ sup) {
    int s0 = blockIdx.x * 16;
    int tid = threadIdx.x;
    __shared__ int nid[16];
    __shared__ float f[16][IND];
    __shared__ float p[16][3];
    if (tid < 16) nid[tid] = sup[s0 + tid];
    __syncthreads();
    for (int id = tid; id < 16 * IND; id += 208)
        f[id >> 4][id & 15] = feat[nid[id >> 4] * IND + (id & 15)];
    if (tid < 48) p[tid / 3][tid % 3] = pos[nid[tid / 3] * 3 + tid % 3];

    int sub = tid / 104;
    int cp = tid % 104;
    int c = 2 * cp;
    bool isfeat = (c < 16);
    int d = 0;
    float om0 = 0.f, om1 = 0.f, b0 = 0.f, b1 = 0.f;
    bool issin = true;
    if (!isfeat) {
        int cu = c - 16;
        d = cu >> 6;
        int t = cu & 63;
        int j = t & 31;
        om0 = exp2f(-(float)j * (13.2877123795494f / 32.0f));
        om1 = exp2f(-(float)(j + 1) * (13.2877123795494f / 32.0f));
        issin = (t < 32);
        b0 = b_in[cu];
        b1 = b_in[cu + 1];
    }
    __syncthreads();

    for (int nn = sub; nn < 16; nn += 2) {
        float v0, v1;
        if (isfeat) {
            v0 = f[nn][c]; v1 = f[nn][c + 1];
        } else {
            float pd = p[nn][d];
            float a0 = pd * om0, a1 = pd * om1;
            v0 = b0 + (issin ? __sinf(a0) : __cosf(a0));
            v1 = b1 + (issin ? __sinf(a1) : __cosf(a1));
        }
        uint16_t h0, l0, h1, l1;
        split_f16(v0, h0, l0);
        split_f16(v1, h1, l1);
        size_t o = (size_t)(s0 + nn) * KA + c;
        *(uint32_t*)(g_sh + o) = (uint32_t)h0 | ((uint32_t)h1 << 16);
        *(uint32_t*)(g_sl + o) = (uint32_t)l0 | ((uint32_t)l1 << 16);
    }
}

// ---------------------------------------------------------------------------
// V = W_in @ W1_{top,bot}: grid 32 (s*16+i), block 192 (n)
// ---------------------------------------------------------------------------
__global__ void vprep_kernel(const float* __restrict__ W_in,
                             const float* __restrict__ W1) {
    int s = blockIdx.x >> 4, i = blockIdx.x & 15, n = threadIdx.x;
    float acc = 0.0f;
    for (int cc = 0; cc < HH; cc++)
        acc = fmaf(W_in[i * HH + cc], W1[(size_t)(cc + s * HH) * HH + n], acc);
    g_v[(s * IND + i) * HH + n] = acc;
}

// ---------------------------------------------------------------------------
// B operands: s<2 -> [V|W1] (KA cols), s==2 -> W2 (HH cols). grid (192,3).
// ---------------------------------------------------------------------------
__global__ void bprep_kernel(const float* __restrict__ W1,
                             const float* __restrict__ W2) {
    int n = blockIdx.x, s = blockIdx.y, k = threadIdx.x;
    if (s < 2) {
        float v = (k < IND) ? g_v[(s * IND + k) * HH + n]
                            : W1[(size_t)(k - IND + s * HH) * HH + n];
        uint16_t h, l;
        split_f16(v, h, l);
        g_b1h[s][n * KA + k] = h;
        g_b1l[s][n * KA + k] = l;
    } else if (k < HH) {
        uint16_t h, l;
        split_f16(W2[(size_t)k * HH + n], h, l);
        g_b2h[n * HH + k] = h;
        g_b2l[n * HH + k] = l;
    }
}

// ---------------------------------------------------------------------------
// Pool: pool[s,c] = mean_e GELU(y[src_e,c] + z[s,c]); split fp16 output.
// ---------------------------------------------------------------------------
__global__ void pool_kernel(const int* __restrict__ src_idx) {
    int tid = threadIdx.x;
    int sgrp = tid / 48;
    int t = tid % 48;
    int s = blockIdx.x * 4 + sgrp;
    int c = t * 4;

    __shared__ int srcs[4][MAXDEG];
    if (tid < 128) srcs[tid >> 5][tid & 31] = src_idx[blockIdx.x * 128 + tid];
    __syncthreads();

    float4 z = *(const float4*)(g_z + (size_t)s * HH + c);
    float4 acc = make_float4(0.f, 0.f, 0.f, 0.f);
#pragma unroll 4
    for (int e = 0; e < MAXDEG; e++) {
        const __half2* yr = (const __half2*)(g_yh + (size_t)srcs[sgrp][e] * HH + c);
        float2 v01 = __half22float2(yr[0]);
        float2 v23 = __half22float2(yr[1]);
        acc.x += gelu_fast(v01.x + z.x);
        acc.y += gelu_fast(v01.y + z.y);
        acc.z += gelu_fast(v23.x + z.z);
        acc.w += gelu_fast(v23.y + z.w);
    }
    const float inv = 1.0f / 32.0f;
    uint16_t h[4], l[4];
    split_f16(acc.x * inv, h[0], l[0]);
    split_f16(acc.y * inv, h[1], l[1]);
    split_f16(acc.z * inv, h[2], l[2]);
    split_f16(acc.w * inv, h[3], l[3]);
    size_t o = (size_t)s * HH + c;
    *(uint2*)(g_ph + o) = make_uint2((uint32_t)h[0] | ((uint32_t)h[1] << 16),
                                     (uint32_t)h[2] | ((uint32_t)h[3] << 16));
    *(uint2*)(g_pl + o) = make_uint2((uint32_t)l[0] | ((uint32_t)l[1] << 16),
                                     (uint32_t)l[2] | ((uint32_t)l[3] << 16));
}

// ---------------------------------------------------------------------------
// launch: R15 fork-join schedule; embed fused into the y-GEMM.
// ---------------------------------------------------------------------------
static cudaStream_t g_s1 = nullptr;
static cudaEvent_t  g_evFork = nullptr, g_evJoin = nullptr;

extern "C" void kernel_launch(void* const* d_in, const int* in_sizes, int n_in,
                              void* d_out, int out_size) {
    const float* feat  = (const float*)d_in[0];
    const float* pos   = (const float*)d_in[1];
    const int*   sup   = (const int*)  d_in[2];
    const int*   src   = (const int*)  d_in[4];
    const float* W_in  = (const float*)d_in[6];
    const float* b_in  = (const float*)d_in[7];
    const float* W1    = (const float*)d_in[8];
    const float* b1    = (const float*)d_in[9];
    const float* W2    = (const float*)d_in[10];
    const float* b2    = (const float*)d_in[11];
    float* out = (float*)d_out;

    if (g_s1 == nullptr) {
        cudaStreamCreateWithFlags(&g_s1, cudaStreamNonBlocking);
        cudaEventCreateWithFlags(&g_evFork, cudaEventDisableTiming);
        cudaEventCreateWithFlags(&g_evJoin, cudaEventDisableTiming);
    }

    uint16_t *psh, *psl, *pph, *ppl, *pb1h, *pb1l, *pb2h, *pb2l;
    __half *pyh;
    float *pz;
    cudaGetSymbolAddress((void**)&psh,  g_sh);
    cudaGetSymbolAddress((void**)&psl,  g_sl);
    cudaGetSymbolAddress((void**)&pyh,  g_yh);
    cudaGetSymbolAddress((void**)&pz,   g_z);
    cudaGetSymbolAddress((void**)&pph,  g_ph);
    cudaGetSymbolAddress((void**)&ppl,  g_pl);
    cudaGetSymbolAddress((void**)&pb1h, g_b1h);
    cudaGetSymbolAddress((void**)&pb1l, g_b1l);
    cudaGetSymbolAddress((void**)&pb2h, g_b2h);
    cudaGetSymbolAddress((void**)&pb2l, g_b2l);

    cudaFuncSetAttribute((const void*)gemm3_kernel<7, true>,
                         cudaFuncAttributeMaxDynamicSharedMemorySize, SMEM_SZ);
    cudaFuncSetAttribute((const void*)gemm3_kernel<6, false>,
                         cudaFuncAttributeMaxDynamicSharedMemorySize, SMEM_SZ);
    cudaFuncSetAttribute((const void*)gemm1f_kernel,
                         cudaFuncAttributeMaxDynamicSharedMemorySize, YSMEM_SZ);

    // prep chain on main stream
    vprep_kernel<<<32, HH>>>(W_in, W1);
    bprep_kernel<<<dim3(HH, 3), KA>>>(W1, W2);

    // fork: side stream does sup_embed + z-GEMM
    cudaEventRecord(g_evFork, 0);
    cudaStreamWaitEvent(g_s1, g_evFork, 0);
    sup_embed_kernel<<<SS / 16, KA, 0, g_s1>>>(feat, pos, b_in, sup);
    gemm3_kernel<7, true><<<(SS / 128) * 2, 256, SMEM_SZ, g_s1>>>(
        psh, psl, pb1h + HH * KA, pb1l + HH * KA, b1, pz);
    cudaEventRecord(g_evJoin, g_s1);

    // main stream: fused embed + y-GEMM
    gemm1f_kernel<<<NN / 128, 256, YSMEM_SZ>>>(feat, pos, b_in, pb1h, pyh);

    // join, then pool + out
    cudaStreamWaitEvent(0, g_evJoin, 0);
    pool_kernel<<<SS / 4, HH>>>(src);
    gemm3_kernel<6, false><<<(SS / 128) * 2, 256, SMEM_SZ>>>(
        pph, ppl, pb2h, pb2l, b2, out);
}